// round 16
// baseline (speedup 1.0000x reference)
#include <cuda_runtime.h>

#define BB 256
#define TT 512
#define EMBD 64
#define HID 128

__device__ float g_pre1[(long)TT * BB * HID];   // [t][b][j], 64 MB

// ---------------------------------------------------------------------------
// Kernel 1: pre1[t][b][j] = dot(emb[x[b,t]], Wih1[j]) + b_ih1[j] + b_hh1[j]
// (proven R1 version, byte-identical)
// ---------------------------------------------------------------------------
__global__ __launch_bounds__(128) void k_pre1(
    const int* __restrict__ x, const float* __restrict__ emb,
    const float* __restrict__ Wih1, const float* __restrict__ bih1,
    const float* __restrict__ bhh1)
{
    __shared__ __align__(16) float shW[HID * 68];
    __shared__ __align__(16) float4 shE[8 * 16];
    __shared__ int shX[8];

    const int tid = threadIdx.x;

    for (int it = 0; it < 64; ++it) {
        int f = it * 128 + tid;
        int j = f >> 6, k = f & 63;
        shW[j * 68 + k] = Wih1[f];
    }
    __syncthreads();

    float Wr[64];
#pragma unroll
    for (int i = 0; i < 64; ++i) Wr[i] = shW[tid * 68 + i];
    const float bb = bih1[tid] + bhh1[tid];

    const int base = blockIdx.x * 256;
    const float4* __restrict__ e4 = (const float4*)emb;

    for (int it = 0; it < 32; ++it) {
        const int rid0 = base + it * 8;             // rid = t*256 + b
        if (tid < 8) {
            int rid = rid0 + tid;
            int t = rid >> 8, b = rid & 255;
            shX[tid] = x[b * TT + t];
        }
        __syncthreads();
        {
            int r = tid >> 4, f = tid & 15;
            shE[r * 16 + f] = e4[(long)shX[r] * 16 + f];
        }
        __syncthreads();

        float acc[8];
#pragma unroll
        for (int r = 0; r < 8; ++r) acc[r] = bb;
#pragma unroll
        for (int k4 = 0; k4 < 16; ++k4) {
#pragma unroll
            for (int r = 0; r < 8; ++r) {
                float4 e = shE[r * 16 + k4];
                acc[r] = fmaf(Wr[4 * k4 + 0], e.x, acc[r]);
                acc[r] = fmaf(Wr[4 * k4 + 1], e.y, acc[r]);
                acc[r] = fmaf(Wr[4 * k4 + 2], e.z, acc[r]);
                acc[r] = fmaf(Wr[4 * k4 + 3], e.w, acc[r]);
            }
        }
#pragma unroll
        for (int r = 0; r < 8; ++r)
            g_pre1[(long)(rid0 + r) * HID + tid] = acc[r];
        __syncthreads();
    }
}

// ---------------------------------------------------------------------------
// Kernel 2: champion's 3-barrier fused scan, k-QUARTER split for 4 warps/SMSP.
// 128 blocks x 512 threads; block handles rows b0, b0+1; 1 CTA/SM.
// Thread (j = tid&127, p = tid>>7 in 0..3) holds quarter-rows (32 floats) of
// W_hh1 / W_ih2 / W_hh2 (96 weight regs). p is warp-uniform.
// Phases (identical math to R15 champion):
//   A: quarter-partials of W_hh1*h1_old (rows 0,1) -> pA            [BAR1]
//   B: p<2:  h1_new = tanhf(pre + sum4(pA)) for row p; prefetch pre [BAR2]
//   C: quarter-partials of W_ih2*h1_new + W_hh2*h2_cur -> pB        [BAR3]
//   D: p>=2: h2_nxt = tanhf(bb2 + sum4(pB)) for row p-2 (no barrier;
//            next BAR1 orders it before C(t+1) reads)
// Fused epilogue (rows handled by p<2 threads).
// ---------------------------------------------------------------------------
__global__ __launch_bounds__(512, 1) void k_scan(
    const float* __restrict__ Whh1, const float* __restrict__ Wih2,
    const float* __restrict__ Whh2, const float* __restrict__ bih2,
    const float* __restrict__ bhh2,
    const float* __restrict__ ln_g, const float* __restrict__ ln_b,
    const float* __restrict__ projW, const float* __restrict__ proj_b,
    const float* __restrict__ on_g, const float* __restrict__ on_b,
    float* __restrict__ out)
{
    __shared__ __align__(16) float sh_h1[2][HID];     // [row][j], in-place
    __shared__ __align__(16) float h2s[2][2][HID];    // [buf][row][j]
    __shared__ __align__(16) float pA[4][2][HID];     // [quarter][row][j]
    __shared__ __align__(16) float pB[4][2][HID];
    __shared__ __align__(16) float rep[2][HID];
    __shared__ float red[2][8];

    const int tid = threadIdx.x;
    const int j = tid & 127;
    const int p = tid >> 7;            // k-quarter, warp-uniform (0..3)
    const int b0 = blockIdx.x * 2;

    // Quarter-rows of the three matrices: 96 weight registers.
    float W1r[32], Wi2r[32], W2r[32];
    {
        const float4* w1 = (const float4*)(Whh1 + j * HID + p * 32);
        const float4* wi = (const float4*)(Wih2 + j * HID + p * 32);
        const float4* w2 = (const float4*)(Whh2 + j * HID + p * 32);
#pragma unroll
        for (int i = 0; i < 8; ++i) {
            float4 a = w1[i];
            W1r[4 * i] = a.x; W1r[4 * i + 1] = a.y; W1r[4 * i + 2] = a.z; W1r[4 * i + 3] = a.w;
            float4 b = wi[i];
            Wi2r[4 * i] = b.x; Wi2r[4 * i + 1] = b.y; Wi2r[4 * i + 2] = b.z; Wi2r[4 * i + 3] = b.w;
            float4 c = w2[i];
            W2r[4 * i] = c.x; W2r[4 * i + 1] = c.y; W2r[4 * i + 2] = c.z; W2r[4 * i + 3] = c.w;
        }
    }

    // Role-specific scalars: pre stream for p<2 (row p); bb2 for p>=2 (row p-2).
    float pre_r = 0.f, bb2 = 0.f;
    const float* preBase = g_pre1 + (long)(b0 + (p & 1)) * HID + j;
    if (p < 2) pre_r = preBase[0];
    else bb2 = bih2[j] + bhh2[j];

    // Zero state.
    if (tid < 256) {
        ((float*)sh_h1)[tid] = 0.f;
        ((float*)h2s)[tid] = 0.f;
        ((float*)h2s)[tid + 256] = 0.f;
    }
    __syncthreads();

    const float4* u0 = (const float4*)&sh_h1[0][p * 32];   // 8 float4 (quarter)
    const float4* u1 = (const float4*)&sh_h1[1][p * 32];
    const float4* h2base = (const float4*)&h2s[0][0][p * 32];  // buf stride 64 f4

    for (int t = 0; t < TT; ++t) {
        const int cur = t & 1, nxt = cur ^ 1;

        // ---- Phase A: W_hh1 * h1_old quarter-partials (rows 0,1) ----
        float a0 = 0.f, a1 = 0.f;
#pragma unroll
        for (int i = 0; i < 8; ++i) {
            float4 h0 = u0[i];
            a0 = fmaf(W1r[4 * i + 0], h0.x, a0);
            a0 = fmaf(W1r[4 * i + 1], h0.y, a0);
            a0 = fmaf(W1r[4 * i + 2], h0.z, a0);
            a0 = fmaf(W1r[4 * i + 3], h0.w, a0);
            float4 h1 = u1[i];
            a1 = fmaf(W1r[4 * i + 0], h1.x, a1);
            a1 = fmaf(W1r[4 * i + 1], h1.y, a1);
            a1 = fmaf(W1r[4 * i + 2], h1.z, a1);
            a1 = fmaf(W1r[4 * i + 3], h1.w, a1);
        }
        pA[p][0][j] = a0;
        pA[p][1][j] = a1;
        __syncthreads();                              // BAR1

        // ---- Phase B: p<2 combines h1 row p; prefetches pre ----
        if (p < 2) {
            float v = pre_r + (pA[0][p][j] + pA[1][p][j])
                            + (pA[2][p][j] + pA[3][p][j]);
            sh_h1[p][j] = tanhf(v);
            if (t + 1 < TT) pre_r = preBase[(long)(t + 1) * BB * HID];
        }
        __syncthreads();                              // BAR2

        // ---- Phase C: W_ih2*h1_new + W_hh2*h2_cur quarter-partials ----
        {
            const float4* g0 = h2base + cur * 64;     // buf cur, row 0
            const float4* g1 = g0 + 32;               // row 1
            float c0 = 0.f, c1 = 0.f, d0 = 0.f, d1 = 0.f;
#pragma unroll
            for (int i = 0; i < 8; ++i) {
                float4 h0 = u0[i];
                c0 = fmaf(Wi2r[4 * i + 0], h0.x, c0);
                c0 = fmaf(Wi2r[4 * i + 1], h0.y, c0);
                c0 = fmaf(Wi2r[4 * i + 2], h0.z, c0);
                c0 = fmaf(Wi2r[4 * i + 3], h0.w, c0);
                float4 h1 = u1[i];
                c1 = fmaf(Wi2r[4 * i + 0], h1.x, c1);
                c1 = fmaf(Wi2r[4 * i + 1], h1.y, c1);
                c1 = fmaf(Wi2r[4 * i + 2], h1.z, c1);
                c1 = fmaf(Wi2r[4 * i + 3], h1.w, c1);
                float4 q0 = g0[i];
                d0 = fmaf(W2r[4 * i + 0], q0.x, d0);
                d0 = fmaf(W2r[4 * i + 1], q0.y, d0);
                d0 = fmaf(W2r[4 * i + 2], q0.z, d0);
                d0 = fmaf(W2r[4 * i + 3], q0.w, d0);
                float4 q1 = g1[i];
                d1 = fmaf(W2r[4 * i + 0], q1.x, d1);
                d1 = fmaf(W2r[4 * i + 1], q1.y, d1);
                d1 = fmaf(W2r[4 * i + 2], q1.z, d1);
                d1 = fmaf(W2r[4 * i + 3], q1.w, d1);
            }
            pB[p][0][j] = c0 + d0;
            pB[p][1][j] = c1 + d1;
        }
        __syncthreads();                              // BAR3

        // ---- Phase D: p>=2 combines h2 row p-2 (no barrier) ----
        if (p >= 2) {
            const int pr = p - 2;
            float v2 = bb2 + (pB[0][pr][j] + pB[1][pr][j])
                           + (pB[2][pr][j] + pB[3][pr][j]);
            h2s[nxt][pr][j] = tanhf(v2);
        }
        // Next BAR1 orders these writes before phase C(t+1) reads them.
    }

    __syncthreads();   // h2 written by p>=2; epilogue read by p<2

    // Final h2 in buf 0 (t=511: nxt = 0).
    // ---- Fused epilogue: rows handled by p<2 threads ----
    const int pr = p & 1;
    const int wg = (tid >> 5) & 3;
    float v = h2s[0][pr][j];

    float s = v, q = v * v;
#pragma unroll
    for (int o = 16; o; o >>= 1) {
        s += __shfl_xor_sync(0xffffffffu, s, o);
        q += __shfl_xor_sync(0xffffffffu, q, o);
    }
    if ((tid & 31) == 0 && p < 2) { red[pr][wg] = s; red[pr][4 + wg] = q; }
    __syncthreads();
    s = red[pr][0] + red[pr][1] + red[pr][2] + red[pr][3];
    q = red[pr][4] + red[pr][5] + red[pr][6] + red[pr][7];
    float mu = s * (1.f / HID);
    float var = q * (1.f / HID) - mu * mu;
    if (p < 2)
        rep[pr][j] = (v - mu) * rsqrtf(var + 1e-5f) * ln_g[j] + ln_b[j];
    __syncthreads();

    float acc = proj_b[j];
    {
        const float4* w4 = (const float4*)(projW + j * HID);
        const float4* r4 = (const float4*)&rep[pr][0];
#pragma unroll
        for (int i = 0; i < 32; ++i) {
            float4 w = __ldg(&w4[i]);
            float4 r = r4[i];
            acc = fmaf(w.x, r.x, acc);
            acc = fmaf(w.y, r.y, acc);
            acc = fmaf(w.z, r.z, acc);
            acc = fmaf(w.w, r.w, acc);
        }
    }
    float tv = tanhf(acc);

    __syncthreads();   // red reuse
    float s2 = tv, q2 = tv * tv;
#pragma unroll
    for (int o = 16; o; o >>= 1) {
        s2 += __shfl_xor_sync(0xffffffffu, s2, o);
        q2 += __shfl_xor_sync(0xffffffffu, q2, o);
    }
    if ((tid & 31) == 0 && p < 2) { red[pr][wg] = s2; red[pr][4 + wg] = q2; }
    __syncthreads();
    s2 = red[pr][0] + red[pr][1] + red[pr][2] + red[pr][3];
    q2 = red[pr][4] + red[pr][5] + red[pr][6] + red[pr][7];
    float mu2 = s2 * (1.f / HID);
    float var2 = q2 * (1.f / HID) - mu2 * mu2;
    if (p < 2)
        out[(b0 + pr) * HID + j] = (tv - mu2) * rsqrtf(var2 + 1e-5f) * on_g[j] + on_b[j];
}

// ---------------------------------------------------------------------------
extern "C" void kernel_launch(void* const* d_in, const int* in_sizes, int n_in,
                              void* d_out, int out_size)
{
    const int*   x     = (const int*)  d_in[0];
    const float* emb   = (const float*)d_in[1];
    const float* Wih1  = (const float*)d_in[2];
    const float* bih1  = (const float*)d_in[3];
    const float* Whh1  = (const float*)d_in[4];
    const float* bhh1  = (const float*)d_in[5];
    const float* Wih2  = (const float*)d_in[6];
    const float* bih2  = (const float*)d_in[7];
    const float* Whh2  = (const float*)d_in[8];
    const float* bhh2  = (const float*)d_in[9];
    const float* ln_g  = (const float*)d_in[10];
    const float* ln_b  = (const float*)d_in[11];
    const float* projW = (const float*)d_in[12];
    const float* projb = (const float*)d_in[13];
    const float* on_g  = (const float*)d_in[14];
    const float* on_b  = (const float*)d_in[15];

    k_pre1<<<512, 128>>>(x, emb, Wih1, bih1, bhh1);
    k_scan<<<128, 512>>>(Whh1, Wih2, Whh2, bih2, bhh2,
                         ln_g, ln_b, projW, projb, on_g, on_b, (float*)d_out);
}

// round 17
// speedup vs baseline: 1.0486x; 1.0486x over previous
#include <cuda_runtime.h>

#define BB 256
#define TT 512
#define EMBD 64
#define HID 128

__device__ float g_pre1[(long)TT * BB * HID];   // [t][b][j], 64 MB

// ---------------------------------------------------------------------------
// Kernel 1: pre1[t][b][j] = dot(emb[x[b,t]], Wih1[j]) + b_ih1[j] + b_hh1[j]
// R1 math, SOFTWARE-PIPELINED: publish staged data, then issue next loads
// (emb gather for it+1, x tokens for it+2) so gather latency overlaps FMA.
// ---------------------------------------------------------------------------
__global__ __launch_bounds__(128) void k_pre1(
    const int* __restrict__ x, const float* __restrict__ emb,
    const float* __restrict__ Wih1, const float* __restrict__ bih1,
    const float* __restrict__ bhh1)
{
    __shared__ __align__(16) float shW[HID * 68];
    __shared__ __align__(16) float4 shE[8 * 16];
    __shared__ int shX[2][8];

    const int tid = threadIdx.x;
    const int r = tid >> 4, f = tid & 15;          // gather role: row, col

    for (int it = 0; it < 64; ++it) {
        int ff = it * 128 + tid;
        int j = ff >> 6, k = ff & 63;
        shW[j * 68 + k] = Wih1[ff];
    }
    __syncthreads();

    float Wr[64];
#pragma unroll
    for (int i = 0; i < 64; ++i) Wr[i] = shW[tid * 68 + i];
    const float bb = bih1[tid] + bhh1[tid];

    const int base = blockIdx.x * 256;              // 256 (b,t) rows per block
    const float4* __restrict__ e4 = (const float4*)emb;

    // ---- Prologue: x(it=0) -> gather emb(0); issue x(it=1) ----
    if (tid < 8) {
        int rid = base + tid;
        shX[0][tid] = x[(rid & 255) * TT + (rid >> 8)];
    }
    __syncthreads();
    float4 ev = e4[(long)shX[0][r] * 16 + f];       // emb for iter 0 (in flight)
    int xv = 0;
    if (tid < 8) {
        int rid = base + 8 + tid;
        xv = x[(rid & 255) * TT + (rid >> 8)];      // tokens for iter 1
    }

    for (int it = 0; it < 32; ++it) {
        const int rid0 = base + it * 8;
        const int nb = (it + 1) & 1;

        // Publish staged data: emb(it) -> shE, tokens(it+1) -> shX[nb]
        shE[r * 16 + f] = ev;
        if (tid < 8) shX[nb][tid] = xv;
        __syncthreads();                            // BAR1

        // Issue next loads (land during the FMA block below)
        if (it + 1 < 32)
            ev = e4[(long)shX[nb][r] * 16 + f];     // emb for it+1
        if (tid < 8 && it + 2 < 32) {
            int rid = rid0 + 16 + tid;
            xv = x[(rid & 255) * TT + (rid >> 8)];  // tokens for it+2
        }

        // Compute pre1 for 8 rows (identical FMA block to champion)
        float acc[8];
#pragma unroll
        for (int rr = 0; rr < 8; ++rr) acc[rr] = bb;
#pragma unroll
        for (int k4 = 0; k4 < 16; ++k4) {
#pragma unroll
            for (int rr = 0; rr < 8; ++rr) {
                float4 e = shE[rr * 16 + k4];
                acc[rr] = fmaf(Wr[4 * k4 + 0], e.x, acc[rr]);
                acc[rr] = fmaf(Wr[4 * k4 + 1], e.y, acc[rr]);
                acc[rr] = fmaf(Wr[4 * k4 + 2], e.z, acc[rr]);
                acc[rr] = fmaf(Wr[4 * k4 + 3], e.w, acc[rr]);
            }
        }
#pragma unroll
        for (int rr = 0; rr < 8; ++rr)
            g_pre1[(long)(rid0 + rr) * HID + tid] = acc[rr];
        __syncthreads();                            // BAR2 (shE WAR guard)
    }
}

// ---------------------------------------------------------------------------
// Kernel 2: R15 CHAMPION scan, byte-identical. 3 barriers/step, double-buffered
// h2, split pA/pB, fused epilogue. 128 blocks x 256 threads, rows b0,b0+1.
// ---------------------------------------------------------------------------
__global__ __launch_bounds__(256, 1) void k_scan(
    const float* __restrict__ Whh1, const float* __restrict__ Wih2,
    const float* __restrict__ Whh2, const float* __restrict__ bih2,
    const float* __restrict__ bhh2,
    const float* __restrict__ ln_g, const float* __restrict__ ln_b,
    const float* __restrict__ projW, const float* __restrict__ proj_b,
    const float* __restrict__ on_g, const float* __restrict__ on_b,
    float* __restrict__ out)
{
    __shared__ __align__(16) float sh_h1[2][HID];     // [row][j], in-place
    __shared__ __align__(16) float h2s[2][2][HID];    // [buf][row][j]
    __shared__ __align__(16) float pA[2][2][HID];     // [half][row][j]
    __shared__ __align__(16) float pB[2][2][HID];     // [half][row][j]
    __shared__ __align__(16) float rep[2][HID];
    __shared__ float red[2][8];

    const int tid = threadIdx.x;
    const int j = tid & 127;
    const int p = tid >> 7;            // k-half (uniform per warp)
    const int b0 = blockIdx.x * 2;

    float W1r[64], Wi2r[64], W2r[64];
    {
        const float* w1 = Whh1 + j * HID + p * 64;
        const float* wi = Wih2 + j * HID + p * 64;
        const float* w2 = Whh2 + j * HID + p * 64;
#pragma unroll
        for (int i = 0; i < 64; ++i) { W1r[i] = w1[i]; Wi2r[i] = wi[i]; W2r[i] = w2[i]; }
    }
    const float bb2 = bih2[j] + bhh2[j];

    sh_h1[p][j] = 0.f;
    h2s[0][p][j] = 0.f;
    h2s[1][p][j] = 0.f;
    __syncthreads();

    const float* preBase = g_pre1 + (long)(b0 + p) * HID + j;
    float pre_r = preBase[0];

    const float4* h10p = (const float4*)&sh_h1[0][p * 64];
    const float4* h11p = (const float4*)&sh_h1[1][p * 64];
    const float4* h2base = (const float4*)&h2s[0][0][p * 64];   // buf stride 64 f4

    for (int t = 0; t < TT; ++t) {
        const int cur = t & 1, nxt = cur ^ 1;

        // ---- Phase A: partials of W_hh1 * h1_old for both rows ----
        float a0 = 0.f, a1 = 0.f;
#pragma unroll
        for (int i = 0; i < 16; ++i) {
            float4 h0 = h10p[i];
            a0 = fmaf(W1r[4 * i + 0], h0.x, a0);
            a0 = fmaf(W1r[4 * i + 1], h0.y, a0);
            a0 = fmaf(W1r[4 * i + 2], h0.z, a0);
            a0 = fmaf(W1r[4 * i + 3], h0.w, a0);
            float4 h1 = h11p[i];
            a1 = fmaf(W1r[4 * i + 0], h1.x, a1);
            a1 = fmaf(W1r[4 * i + 1], h1.y, a1);
            a1 = fmaf(W1r[4 * i + 2], h1.z, a1);
            a1 = fmaf(W1r[4 * i + 3], h1.w, a1);
        }
        pA[p][0][j] = a0;
        pA[p][1][j] = a1;
        __syncthreads();                              // BAR1

        // ---- Phase B: h1_new = tanh(pre + sum) for row p ----
        {
            float v = pre_r + pA[0][p][j] + pA[1][p][j];
            sh_h1[p][j] = tanhf(v);
        }
        if (t + 1 < TT) pre_r = preBase[(long)(t + 1) * BB * HID];
        __syncthreads();                              // BAR2

        // ---- Phase C: partials of W_ih2*h1_new + W_hh2*h2_cur ----
        {
            const float4* g0 = h2base + cur * 64;     // buf cur, row 0
            const float4* g1 = g0 + 32;               // row 1
            float c0 = 0.f, c1 = 0.f, d0 = 0.f, d1 = 0.f;
#pragma unroll
            for (int i = 0; i < 16; ++i) {
                float4 h0 = h10p[i];
                c0 = fmaf(Wi2r[4 * i + 0], h0.x, c0);
                c0 = fmaf(Wi2r[4 * i + 1], h0.y, c0);
                c0 = fmaf(Wi2r[4 * i + 2], h0.z, c0);
                c0 = fmaf(Wi2r[4 * i + 3], h0.w, c0);
                float4 h1 = h11p[i];
                c1 = fmaf(Wi2r[4 * i + 0], h1.x, c1);
                c1 = fmaf(Wi2r[4 * i + 1], h1.y, c1);
                c1 = fmaf(Wi2r[4 * i + 2], h1.z, c1);
                c1 = fmaf(Wi2r[4 * i + 3], h1.w, c1);
                float4 u0 = g0[i];
                d0 = fmaf(W2r[4 * i + 0], u0.x, d0);
                d0 = fmaf(W2r[4 * i + 1], u0.y, d0);
                d0 = fmaf(W2r[4 * i + 2], u0.z, d0);
                d0 = fmaf(W2r[4 * i + 3], u0.w, d0);
                float4 u1 = g1[i];
                d1 = fmaf(W2r[4 * i + 0], u1.x, d1);
                d1 = fmaf(W2r[4 * i + 1], u1.y, d1);
                d1 = fmaf(W2r[4 * i + 2], u1.z, d1);
                d1 = fmaf(W2r[4 * i + 3], u1.w, d1);
            }
            pB[p][0][j] = c0 + d0;
            pB[p][1][j] = c1 + d1;
        }
        __syncthreads();                              // BAR3

        // ---- Phase D: h2_nxt = tanh(bb2 + sum) for row p (no barrier) ----
        {
            float v2 = bb2 + pB[0][p][j] + pB[1][p][j];
            h2s[nxt][p][j] = tanhf(v2);
        }
        // Next BAR1 orders this write before phase C(t+1) reads it.
    }

    // Final h2 in buf 0 (t=511 wrote nxt = 0); own element, no sync needed.
    const int wg = (tid >> 5) & 3;
    float v = h2s[0][p][j];

    // ---- LN 1 over row p ----
    float s = v, q = v * v;
#pragma unroll
    for (int o = 16; o; o >>= 1) {
        s += __shfl_xor_sync(0xffffffffu, s, o);
        q += __shfl_xor_sync(0xffffffffu, q, o);
    }
    if ((tid & 31) == 0) { red[p][wg] = s; red[p][4 + wg] = q; }
    __syncthreads();
    s = red[p][0] + red[p][1] + red[p][2] + red[p][3];
    q = red[p][4] + red[p][5] + red[p][6] + red[p][7];
    float mu = s * (1.f / HID);
    float var = q * (1.f / HID) - mu * mu;
    rep[p][j] = (v - mu) * rsqrtf(var + 1e-5f) * ln_g[j] + ln_b[j];
    __syncthreads();

    // ---- proj + tanh ----
    float acc = proj_b[j];
    {
        const float4* w4 = (const float4*)(projW + j * HID);
        const float4* r4 = (const float4*)&rep[p][0];
#pragma unroll
        for (int i = 0; i < 32; ++i) {
            float4 w = __ldg(&w4[i]);
            float4 r = r4[i];
            acc = fmaf(w.x, r.x, acc);
            acc = fmaf(w.y, r.y, acc);
            acc = fmaf(w.z, r.z, acc);
            acc = fmaf(w.w, r.w, acc);
        }
    }
    float tv = tanhf(acc);

    // ---- LN 2 ----
    __syncthreads();   // red reuse
    float s2 = tv, q2 = tv * tv;
#pragma unroll
    for (int o = 16; o; o >>= 1) {
        s2 += __shfl_xor_sync(0xffffffffu, s2, o);
        q2 += __shfl_xor_sync(0xffffffffu, q2, o);
    }
    if ((tid & 31) == 0) { red[p][wg] = s2; red[p][4 + wg] = q2; }
    __syncthreads();
    s2 = red[p][0] + red[p][1] + red[p][2] + red[p][3];
    q2 = red[p][4] + red[p][5] + red[p][6] + red[p][7];
    float mu2 = s2 * (1.f / HID);
    float var2 = q2 * (1.f / HID) - mu2 * mu2;
    out[(b0 + p) * HID + j] = (tv - mu2) * rsqrtf(var2 + 1e-5f) * on_g[j] + on_b[j];
}

// ---------------------------------------------------------------------------
extern "C" void kernel_launch(void* const* d_in, const int* in_sizes, int n_in,
                              void* d_out, int out_size)
{
    const int*   x     = (const int*)  d_in[0];
    const float* emb   = (const float*)d_in[1];
    const float* Wih1  = (const float*)d_in[2];
    const float* bih1  = (const float*)d_in[3];
    const float* Whh1  = (const float*)d_in[4];
    const float* bhh1  = (const float*)d_in[5];
    const float* Wih2  = (const float*)d_in[6];
    const float* bih2  = (const float*)d_in[7];
    const float* Whh2  = (const float*)d_in[8];
    const float* bhh2  = (const float*)d_in[9];
    const float* ln_g  = (const float*)d_in[10];
    const float* ln_b  = (const float*)d_in[11];
    const float* projW = (const float*)d_in[12];
    const float* projb = (const float*)d_in[13];
    const float* on_g  = (const float*)d_in[14];
    const float* on_b  = (const float*)d_in[15];

    k_pre1<<<512, 128>>>(x, emb, Wih1, bih1, bhh1);
    k_scan<<<128, 256>>>(Whh1, Wih2, Whh2, bih2, bhh2,
                         ln_g, ln_b, projW, projb, on_g, on_b, (float*)d_out);
}